// round 1
// baseline (speedup 1.0000x reference)
#include <cuda_runtime.h>
#include <cuda_bf16.h>
#include <math.h>

// Problem constants (fixed shapes for StackedAdapter_50689204027520)
#define BATCH   32
#define SEQ     512
#define DIM     1024
#define FFN     2048
#define GDOM    4
#define NTOK    (BATCH * SEQ)          // 16384
#define LN_EPS  1e-6f

// ---------------------------------------------------------------------------
// Scratch (device globals: allocation-free per harness rules)
// ---------------------------------------------------------------------------
__device__ float g_ln[(size_t)NTOK * DIM];   // 64 MB: layernormed activations
__device__ float g_h [(size_t)NTOK * FFN];   // 128 MB: relu(ln@W1 + b1)
__device__ int   g_dom[BATCH];               // batch row -> domain group

// ---------------------------------------------------------------------------
// K0: invert idx[4][8] into batch->domain map
// ---------------------------------------------------------------------------
__global__ void dom_kernel(const int* __restrict__ idx) {
    int i = threadIdx.x;
    if (i < GDOM * (BATCH / GDOM)) {
        g_dom[idx[i]] = i >> 3;   // i/8 = domain group
    }
}

// ---------------------------------------------------------------------------
// K1: LayerNorm (torch semantics: g*(x-mu)/(std_ddof1 + eps) + b)
// one block per token, 256 threads, float4 per thread (D=1024)
// ---------------------------------------------------------------------------
__global__ __launch_bounds__(256)
void ln_kernel(const float* __restrict__ x,
               const float* __restrict__ G,
               const float* __restrict__ Bn) {
    const int r     = blockIdx.x;          // token row
    const int batch = r >> 9;              // / SEQ
    const int g     = g_dom[batch];
    const int tid   = threadIdx.x;

    const float4 v = ((const float4*)(x + (size_t)r * DIM))[tid];
    float s  = v.x + v.y + v.z + v.w;
    float ss = v.x*v.x + v.y*v.y + v.z*v.z + v.w*v.w;

    // block reduce (256 threads = 8 warps)
    __shared__ float red_s[8], red_ss[8];
    #pragma unroll
    for (int o = 16; o > 0; o >>= 1) {
        s  += __shfl_down_sync(0xffffffffu, s,  o);
        ss += __shfl_down_sync(0xffffffffu, ss, o);
    }
    if ((tid & 31) == 0) { red_s[tid >> 5] = s; red_ss[tid >> 5] = ss; }
    __syncthreads();

    __shared__ float s_mu, s_inv;
    if (tid == 0) {
        float ts = 0.f, tss = 0.f;
        #pragma unroll
        for (int i = 0; i < 8; i++) { ts += red_s[i]; tss += red_ss[i]; }
        float mu  = ts * (1.0f / DIM);
        float var = (tss - (float)DIM * mu * mu) * (1.0f / (DIM - 1)); // ddof=1
        var = fmaxf(var, 0.0f);
        s_mu  = mu;
        s_inv = 1.0f / (sqrtf(var) + LN_EPS);   // eps added to STD, not var
    }
    __syncthreads();

    const float mu = s_mu, inv = s_inv;
    const float4 gv = ((const float4*)(G  + (size_t)g * DIM))[tid];
    const float4 bv = ((const float4*)(Bn + (size_t)g * DIM))[tid];
    float4 y;
    y.x = gv.x * (v.x - mu) * inv + bv.x;
    y.y = gv.y * (v.y - mu) * inv + bv.y;
    y.z = gv.z * (v.z - mu) * inv + bv.z;
    y.w = gv.w * (v.w - mu) * inv + bv.w;
    ((float4*)(g_ln + (size_t)r * DIM))[tid] = y;
}

// ---------------------------------------------------------------------------
// K2/K3: grouped SGEMM, 128x128 CTA tile, BK=8, 256 threads, 8x8 per thread.
// C[m][n] = epilogue( sum_k A[m][k] * Bw[g][k][n] )
// Rows are token-ordered; each 128-row tile lies inside one batch (128|512),
// so the domain g is uniform per CTA.
// ---------------------------------------------------------------------------
#define BM 128
#define BN 128
#define BK 8
#define TM 8
#define TN 8

template<bool RELU, bool RESID>
__global__ __launch_bounds__(256)
void gemm_kernel(const float* __restrict__ A,
                 const float* __restrict__ Bw,
                 const float* __restrict__ bias,
                 const float* __restrict__ resid,
                 float* __restrict__ C,
                 int N, int K) {
    const int col0 = blockIdx.x * BN;
    const int row0 = blockIdx.y * BM;
    const int g    = g_dom[row0 >> 9];   // row0 / SEQ
    const float* Bg = Bw + (size_t)g * K * N;

    __shared__ float As[BK][BM];
    __shared__ float Bs[BK][BN];

    const int tid  = threadIdx.x;
    // A tile load: 128x8 floats = 256 float4; 2 float4 per A row
    const int aRow = tid >> 1;
    const int aCol = (tid & 1) << 2;
    // B tile load: 8x128 floats = 256 float4; 32 float4 per B row
    const int bRow = tid >> 5;
    const int bCol = (tid & 31) << 2;
    // 16x16 thread grid, each thread 8x8 outputs
    const int tr = (tid >> 4) * TM;
    const int tc = (tid & 15) * TN;

    const float* Aptr = A  + (size_t)(row0 + aRow) * K + aCol;
    const float* Bptr = Bg + (size_t)bRow * N + col0 + bCol;

    float acc[TM][TN] = {};

    for (int k0 = 0; k0 < K; k0 += BK) {
        float4 av = *(const float4*)(Aptr + k0);
        As[aCol + 0][aRow] = av.x;
        As[aCol + 1][aRow] = av.y;
        As[aCol + 2][aRow] = av.z;
        As[aCol + 3][aRow] = av.w;
        *(float4*)&Bs[bRow][bCol] = *(const float4*)(Bptr + (size_t)k0 * N);
        __syncthreads();

        #pragma unroll
        for (int kk = 0; kk < BK; kk++) {
            float ra[TM], rb[TN];
            *(float4*)&ra[0] = *(const float4*)&As[kk][tr];
            *(float4*)&ra[4] = *(const float4*)&As[kk][tr + 4];
            *(float4*)&rb[0] = *(const float4*)&Bs[kk][tc];
            *(float4*)&rb[4] = *(const float4*)&Bs[kk][tc + 4];
            #pragma unroll
            for (int i = 0; i < TM; i++)
                #pragma unroll
                for (int j = 0; j < TN; j++)
                    acc[i][j] = fmaf(ra[i], rb[j], acc[i][j]);
        }
        __syncthreads();
    }

    // epilogue: bias (+relu) (+residual), vectorized float4
    const float* biasg = bias + (size_t)g * N;
    float4 bfrag0 = *(const float4*)(biasg + col0 + tc);
    float4 bfrag1 = *(const float4*)(biasg + col0 + tc + 4);

    #pragma unroll
    for (int i = 0; i < TM; i++) {
        const int r = row0 + tr + i;
        float* crow = C + (size_t)r * N + col0 + tc;
        float4 v0, v1;
        v0.x = acc[i][0] + bfrag0.x;  v0.y = acc[i][1] + bfrag0.y;
        v0.z = acc[i][2] + bfrag0.z;  v0.w = acc[i][3] + bfrag0.w;
        v1.x = acc[i][4] + bfrag1.x;  v1.y = acc[i][5] + bfrag1.y;
        v1.z = acc[i][6] + bfrag1.z;  v1.w = acc[i][7] + bfrag1.w;
        if (RELU) {
            v0.x = fmaxf(v0.x, 0.f); v0.y = fmaxf(v0.y, 0.f);
            v0.z = fmaxf(v0.z, 0.f); v0.w = fmaxf(v0.w, 0.f);
            v1.x = fmaxf(v1.x, 0.f); v1.y = fmaxf(v1.y, 0.f);
            v1.z = fmaxf(v1.z, 0.f); v1.w = fmaxf(v1.w, 0.f);
        }
        if (RESID) {
            const float* rrow = resid + (size_t)r * N + col0 + tc;
            float4 x0 = *(const float4*)(rrow);
            float4 x1 = *(const float4*)(rrow + 4);
            v0.x += x0.x; v0.y += x0.y; v0.z += x0.z; v0.w += x0.w;
            v1.x += x1.x; v1.y += x1.y; v1.z += x1.z; v1.w += x1.w;
        }
        *(float4*)(crow)     = v0;
        *(float4*)(crow + 4) = v1;
    }
}

// A-side pointers for scratch (device globals referenced via tiny shim kernels
// would cost a launch; instead expose through wrappers that take the symbol).
__global__ __launch_bounds__(256)
void gemm1_wrap(const float* __restrict__ W1, const float* __restrict__ B1) {
    // never launched; placeholder to keep template instantiations (unused)
}

extern "C" void kernel_launch(void* const* d_in, const int* in_sizes, int n_in,
                              void* d_out, int out_size) {
    const float* x   = (const float*)d_in[0];
    const int*   idx = (const int*)  d_in[1];
    const float* W1  = (const float*)d_in[2];
    const float* B1  = (const float*)d_in[3];
    const float* W2  = (const float*)d_in[4];
    const float* B2  = (const float*)d_in[5];
    const float* G   = (const float*)d_in[6];
    const float* Bn  = (const float*)d_in[7];
    float*       out = (float*)d_out;

    // scratch symbol addresses (device globals; resolved at module load, no alloc)
    float* ln_ptr = nullptr;
    float* h_ptr  = nullptr;
    cudaGetSymbolAddress((void**)&ln_ptr, g_ln);
    cudaGetSymbolAddress((void**)&h_ptr,  g_h);

    // K0: batch -> domain
    dom_kernel<<<1, 32>>>(idx);

    // K1: layernorm into g_ln
    ln_kernel<<<NTOK, 256>>>(x, G, Bn);

    // K2: h = relu(ln @ W1[g] + B1[g])   (M=16384, K=1024, N=2048)
    {
        dim3 grid(FFN / BN, NTOK / BM);
        gemm_kernel<true, false><<<grid, 256>>>(ln_ptr, W1, B1, nullptr, h_ptr,
                                                FFN, DIM);
    }

    // K3: out = x + h @ W2[g] + B2[g]    (M=16384, K=2048, N=1024)
    {
        dim3 grid(DIM / BN, NTOK / BM);
        gemm_kernel<false, true><<<grid, 256>>>(h_ptr, W2, B2, x, out,
                                                DIM, FFN);
    }
}

// round 4
// speedup vs baseline: 3.3556x; 3.3556x over previous
#include <cuda_runtime.h>
#include <math.h>
#include <stdint.h>

// Problem constants
#define BATCH   32
#define SEQ     512
#define DIM     1024
#define FFN     2048
#define GDOM    4
#define NTOK    (BATCH * SEQ)
#define LN_EPS  1e-6f

// GEMM tiling: 128x128 CTA, BK=16, 8 warps (2m x 4n), warp tile 64x32
#define BM 128
#define BN 128
#define BKK 16
#define NSTG 4
#define PAD_STRIDE 20                       // words per k-row (16 data + 4 pad)
#define STAGE_WORDS (128 * PAD_STRIDE)      // 2560 words per operand per stage
#define SMEM_BYTES (NSTG * 2 * STAGE_WORDS * 4)   // 81920

// ---------------------------------------------------------------------------
// Scratch (device globals; allocation-free per harness rules)
// ---------------------------------------------------------------------------
__device__ float g_ln [(size_t)NTOK * DIM];       // tf32-rounded LN output
__device__ float g_h  [(size_t)NTOK * FFN];       // tf32-rounded hidden
__device__ float g_w1t[(size_t)GDOM * FFN * DIM]; // W1^T [g][F][D] tf32
__device__ float g_w2t[(size_t)GDOM * DIM * FFN]; // W2^T [g][D][F] tf32
__device__ int   g_dom[BATCH];

// ---------------------------------------------------------------------------
// PTX helpers (sm_100-safe: cp.async + mma.sync only)
// ---------------------------------------------------------------------------
__device__ __forceinline__ uint32_t smem_u32(const void* p) {
    uint32_t a;
    asm("{ .reg .u64 t; cvta.to.shared.u64 t, %1; cvt.u32.u64 %0, t; }"
        : "=r"(a) : "l"(p));
    return a;
}
// cvt.rna.tf32.f32 writes a .b32 destination (tf32 bit-pattern is fp32 with
// low 13 mantissa bits zeroed) -> use "=r" and bitcast back.
__device__ __forceinline__ float rna_tf32(float x) {
    uint32_t y;
    asm("cvt.rna.tf32.f32 %0, %1;" : "=r"(y) : "f"(x));
    return __uint_as_float(y);
}
__device__ __forceinline__ void cp_async16(void* s, const void* g) {
    uint32_t sa = smem_u32(s);
    asm volatile("cp.async.cg.shared.global [%0], [%1], 16;" :: "r"(sa), "l"(g));
}
#define CP_COMMIT() asm volatile("cp.async.commit_group;" ::: "memory")
#define CP_WAIT(n)  asm volatile("cp.async.wait_group %0;" :: "n"(n) : "memory")

// D += A*B for m16n8k8 row.col tf32
__device__ __forceinline__ void mma_tf32(float* c, const uint32_t* a,
                                         const uint32_t* b) {
    asm volatile(
        "mma.sync.aligned.m16n8k8.row.col.f32.tf32.tf32.f32 "
        "{%0,%1,%2,%3}, {%4,%5,%6,%7}, {%8,%9}, {%0,%1,%2,%3};"
        : "+f"(c[0]), "+f"(c[1]), "+f"(c[2]), "+f"(c[3])
        : "r"(a[0]), "r"(a[1]), "r"(a[2]), "r"(a[3]), "r"(b[0]), "r"(b[1]));
}

// ---------------------------------------------------------------------------
// K0: batch -> domain
// ---------------------------------------------------------------------------
__global__ void dom_kernel(const int* __restrict__ idx) {
    int i = threadIdx.x;
    if (i < BATCH) g_dom[idx[i]] = i >> 3;
}

// ---------------------------------------------------------------------------
// K1: transpose + tf32-round weights: W[g][R][C] -> Wt[g][C][R]
// ---------------------------------------------------------------------------
__global__ __launch_bounds__(256)
void transpose_kernel(const float* __restrict__ W, float* __restrict__ Wt,
                      int R, int C) {
    __shared__ float t[32][33];
    const int g  = blockIdx.z;
    const int r0 = blockIdx.y * 32;
    const int c0 = blockIdx.x * 32;
    const float* Wg  = W  + (size_t)g * R * C;
    float*       Wtg = Wt + (size_t)g * R * C;
    const int tx = threadIdx.x & 31;
    const int ty = threadIdx.x >> 5;
    #pragma unroll
    for (int i = 0; i < 32; i += 8)
        t[ty + i][tx] = rna_tf32(Wg[(size_t)(r0 + ty + i) * C + c0 + tx]);
    __syncthreads();
    #pragma unroll
    for (int i = 0; i < 32; i += 8)
        Wtg[(size_t)(c0 + ty + i) * R + r0 + tx] = t[tx][ty + i];
}

// ---------------------------------------------------------------------------
// K2: LayerNorm (torch: g*(x-mu)/(std_ddof1+eps)+b), tf32-rounded output
// ---------------------------------------------------------------------------
__global__ __launch_bounds__(256)
void ln_kernel(const float* __restrict__ x,
               const float* __restrict__ G,
               const float* __restrict__ Bn) {
    const int r   = blockIdx.x;
    const int g   = g_dom[r >> 9];
    const int tid = threadIdx.x;

    const float4 v = ((const float4*)(x + (size_t)r * DIM))[tid];
    float s  = v.x + v.y + v.z + v.w;
    float ss = v.x * v.x + v.y * v.y + v.z * v.z + v.w * v.w;

    __shared__ float red_s[8], red_ss[8];
    #pragma unroll
    for (int o = 16; o > 0; o >>= 1) {
        s  += __shfl_down_sync(0xffffffffu, s,  o);
        ss += __shfl_down_sync(0xffffffffu, ss, o);
    }
    if ((tid & 31) == 0) { red_s[tid >> 5] = s; red_ss[tid >> 5] = ss; }
    __syncthreads();
    __shared__ float s_mu, s_inv;
    if (tid == 0) {
        float ts = 0.f, tss = 0.f;
        #pragma unroll
        for (int i = 0; i < 8; i++) { ts += red_s[i]; tss += red_ss[i]; }
        float mu  = ts * (1.0f / DIM);
        float var = (tss - (float)DIM * mu * mu) * (1.0f / (DIM - 1));
        var = fmaxf(var, 0.0f);
        s_mu  = mu;
        s_inv = 1.0f / (sqrtf(var) + LN_EPS);
    }
    __syncthreads();
    const float mu = s_mu, inv = s_inv;
    const float4 gv = ((const float4*)(G  + (size_t)g * DIM))[tid];
    const float4 bv = ((const float4*)(Bn + (size_t)g * DIM))[tid];
    float4 y;
    y.x = rna_tf32(gv.x * (v.x - mu) * inv + bv.x);
    y.y = rna_tf32(gv.y * (v.y - mu) * inv + bv.y);
    y.z = rna_tf32(gv.z * (v.z - mu) * inv + bv.z);
    y.w = rna_tf32(gv.w * (v.w - mu) * inv + bv.w);
    ((float4*)(g_ln + (size_t)r * DIM))[tid] = y;
}

// ---------------------------------------------------------------------------
// K3/K4: tf32 mma.sync grouped GEMM. C[m][n] = epi(sum_k A[m][k]*Bt[g][n][k])
// ---------------------------------------------------------------------------
template<bool RELU, bool RESID, bool ROUND_OUT>
__global__ __launch_bounds__(256, 2)
void mma_gemm(const float* __restrict__ A, const float* __restrict__ Bt,
              const float* __restrict__ bias, const float* __restrict__ resid,
              float* __restrict__ C, int N, int K) {
    extern __shared__ float sm[];
    const int tid  = threadIdx.x;
    const int row0 = blockIdx.y * BM;
    const int col0 = blockIdx.x * BN;
    const int g    = g_dom[row0 >> 9];
    const float* Bg = Bt + (size_t)g * N * K;

    const int lane  = tid & 31;
    const int wid   = tid >> 5;
    const int gid   = lane >> 2;      // 0..7
    const int tg    = lane & 3;       // 0..3
    const int warpm = wid & 1;        // 0..1 -> m offset *64
    const int warpn = wid >> 1;       // 0..3 -> n offset *32

    // per-thread global-load coords: 512 16B-chunks per operand, 2 per thread
    auto load_stage = [&](int kt, int s) {
        const int k0 = kt * BKK;
        float* As = sm + s * 2 * STAGE_WORDS;
        float* Bs = As + STAGE_WORDS;
        #pragma unroll
        for (int j = 0; j < 2; j++) {
            int c = tid + j * 256;
            int m = c >> 2, kc = (c & 3) << 2;
            cp_async16(&As[m * PAD_STRIDE + kc],
                       A + (size_t)(row0 + m) * K + k0 + kc);
        }
        #pragma unroll
        for (int j = 0; j < 2; j++) {
            int c = tid + j * 256;
            int n = c >> 2, kc = (c & 3) << 2;
            cp_async16(&Bs[n * PAD_STRIDE + kc],
                       Bg + (size_t)(col0 + n) * K + k0 + kc);
        }
        CP_COMMIT();
    };

    float acc[4][4][4];
    #pragma unroll
    for (int i = 0; i < 4; i++)
        #pragma unroll
        for (int j = 0; j < 4; j++)
            #pragma unroll
            for (int q = 0; q < 4; q++) acc[i][j][q] = 0.f;

    const int KT = K / BKK;
    #pragma unroll
    for (int s = 0; s < NSTG - 1; s++) load_stage(s, s);

    for (int kt = 0; kt < KT; kt++) {
        CP_WAIT(NSTG - 2);
        __syncthreads();
        // refill the slot computed last iteration
        {
            int nx = kt + NSTG - 1;
            if (nx < KT) load_stage(nx, nx & (NSTG - 1));
            else CP_COMMIT();
        }
        const float* As = sm + (kt & (NSTG - 1)) * 2 * STAGE_WORDS;
        const float* Bs = As + STAGE_WORDS;
        const float* Abase = As + (warpm * 64 + gid) * PAD_STRIDE;
        const float* Bbase = Bs + (warpn * 32 + gid) * PAD_STRIDE;
        #pragma unroll
        for (int ks = 0; ks < 2; ks++) {
            uint32_t a[4][4], b[4][2];
            #pragma unroll
            for (int mf = 0; mf < 4; mf++) {
                const float* p = Abase + mf * 16 * PAD_STRIDE + ks * 8 + tg;
                a[mf][0] = __float_as_uint(p[0]);
                a[mf][1] = __float_as_uint(p[8 * PAD_STRIDE]);
                a[mf][2] = __float_as_uint(p[4]);
                a[mf][3] = __float_as_uint(p[8 * PAD_STRIDE + 4]);
            }
            #pragma unroll
            for (int nf = 0; nf < 4; nf++) {
                const float* p = Bbase + nf * 8 * PAD_STRIDE + ks * 8 + tg;
                b[nf][0] = __float_as_uint(p[0]);
                b[nf][1] = __float_as_uint(p[4]);
            }
            #pragma unroll
            for (int mf = 0; mf < 4; mf++)
                #pragma unroll
                for (int nf = 0; nf < 4; nf++)
                    mma_tf32(acc[mf][nf], a[mf], b[nf]);
        }
    }

    // epilogue: bias (+relu) (+residual) (+tf32 round), float2 stores
    const float* biasg = bias + (size_t)g * N;
    #pragma unroll
    for (int mf = 0; mf < 4; mf++) {
        #pragma unroll
        for (int h = 0; h < 2; h++) {
            const int r = row0 + warpm * 64 + mf * 16 + gid + h * 8;
            float* crow = C + (size_t)r * N;
            const float* rrow = RESID ? (resid + (size_t)r * N) : nullptr;
            #pragma unroll
            for (int nf = 0; nf < 4; nf++) {
                const int cidx = col0 + warpn * 32 + nf * 8 + tg * 2;
                float2 v;
                v.x = acc[mf][nf][h * 2 + 0] + biasg[cidx];
                v.y = acc[mf][nf][h * 2 + 1] + biasg[cidx + 1];
                if (RELU) { v.x = fmaxf(v.x, 0.f); v.y = fmaxf(v.y, 0.f); }
                if (RESID) { v.x += rrow[cidx]; v.y += rrow[cidx + 1]; }
                if (ROUND_OUT) { v.x = rna_tf32(v.x); v.y = rna_tf32(v.y); }
                *(float2*)(crow + cidx) = v;
            }
        }
    }
}

// ---------------------------------------------------------------------------
extern "C" void kernel_launch(void* const* d_in, const int* in_sizes, int n_in,
                              void* d_out, int out_size) {
    const float* x   = (const float*)d_in[0];
    const int*   idx = (const int*)  d_in[1];
    const float* W1  = (const float*)d_in[2];
    const float* B1  = (const float*)d_in[3];
    const float* W2  = (const float*)d_in[4];
    const float* B2  = (const float*)d_in[5];
    const float* G   = (const float*)d_in[6];
    const float* Bn  = (const float*)d_in[7];
    float*       out = (float*)d_out;

    float *ln_ptr, *h_ptr, *w1t_ptr, *w2t_ptr;
    cudaGetSymbolAddress((void**)&ln_ptr,  g_ln);
    cudaGetSymbolAddress((void**)&h_ptr,   g_h);
    cudaGetSymbolAddress((void**)&w1t_ptr, g_w1t);
    cudaGetSymbolAddress((void**)&w2t_ptr, g_w2t);

    static bool attr_done = false;
    if (!attr_done) {
        cudaFuncSetAttribute(mma_gemm<true, false, true>,
                             cudaFuncAttributeMaxDynamicSharedMemorySize, SMEM_BYTES);
        cudaFuncSetAttribute(mma_gemm<false, true, false>,
                             cudaFuncAttributeMaxDynamicSharedMemorySize, SMEM_BYTES);
        attr_done = true;
    }

    dom_kernel<<<1, 32>>>(idx);

    // W1[g][D][F] -> g_w1t[g][F][D];  W2[g][F][D] -> g_w2t[g][D][F]
    transpose_kernel<<<dim3(FFN / 32, DIM / 32, GDOM), 256>>>(W1, w1t_ptr, DIM, FFN);
    transpose_kernel<<<dim3(DIM / 32, FFN / 32, GDOM), 256>>>(W2, w2t_ptr, FFN, DIM);

    ln_kernel<<<NTOK, 256>>>(x, G, Bn);

    // gemm1: h = relu(ln @ W1[g] + B1[g]), tf32-rounded out
    mma_gemm<true, false, true><<<dim3(FFN / BN, NTOK / BM), 256, SMEM_BYTES>>>(
        ln_ptr, w1t_ptr, B1, nullptr, h_ptr, FFN, DIM);

    // gemm2: out = x + h @ W2[g] + B2[g]
    mma_gemm<false, true, false><<<dim3(DIM / BN, NTOK / BM), 256, SMEM_BYTES>>>(
        h_ptr, w2t_ptr, B2, x, out, DIM, FFN);
}

// round 5
// speedup vs baseline: 6.0703x; 1.8090x over previous
#include <cuda_runtime.h>
#include <cuda_fp16.h>
#include <math.h>
#include <stdint.h>

// Problem constants
#define BATCH   32
#define SEQ     512
#define DIM     1024
#define FFN     2048
#define GDOM    4
#define NTOK    (BATCH * SEQ)
#define LN_EPS  1e-6f

// GEMM tiling: 128x128 CTA, BK=32 (halves), 8 warps (2m x 4n), warp 64x32
#define BM 128
#define BN 128
#define BKK 32
#define NSTG 4
#define PADH 40                              // halves per k-row (32 data + 8 pad)
#define STAGE_HALVES (128 * PADH)            // 5120 halves per operand stage
#define SMEM_BYTES (NSTG * 2 * STAGE_HALVES * 2)   // 81920

// ---------------------------------------------------------------------------
// Scratch (device globals; allocation-free per harness rules)
// ---------------------------------------------------------------------------
__device__ __half g_ln [(size_t)NTOK * DIM];        // 32 MB LN output (fp16)
__device__ __half g_h  [(size_t)NTOK * FFN];        // 64 MB hidden (fp16)
__device__ __half g_w1t[(size_t)GDOM * FFN * DIM];  // 16 MB W1^T [g][F][D]
__device__ __half g_w2t[(size_t)GDOM * DIM * FFN];  // 16 MB W2^T [g][D][F]
__device__ int    g_dom[BATCH];

// ---------------------------------------------------------------------------
// PTX helpers
// ---------------------------------------------------------------------------
__device__ __forceinline__ uint32_t smem_u32(const void* p) {
    uint32_t a;
    asm("{ .reg .u64 t; cvta.to.shared.u64 t, %1; cvt.u32.u64 %0, t; }"
        : "=r"(a) : "l"(p));
    return a;
}
__device__ __forceinline__ void cp_async16(void* s, const void* g) {
    uint32_t sa = smem_u32(s);
    asm volatile("cp.async.cg.shared.global [%0], [%1], 16;" :: "r"(sa), "l"(g));
}
#define CP_COMMIT() asm volatile("cp.async.commit_group;" ::: "memory")
#define CP_WAIT(n)  asm volatile("cp.async.wait_group %0;" :: "n"(n) : "memory")

// D += A*B, m16n8k16 row.col f16 inputs, f32 accum
__device__ __forceinline__ void mma_f16(float* c, const uint32_t* a,
                                        const uint32_t* b) {
    asm volatile(
        "mma.sync.aligned.m16n8k16.row.col.f32.f16.f16.f32 "
        "{%0,%1,%2,%3}, {%4,%5,%6,%7}, {%8,%9}, {%0,%1,%2,%3};"
        : "+f"(c[0]), "+f"(c[1]), "+f"(c[2]), "+f"(c[3])
        : "r"(a[0]), "r"(a[1]), "r"(a[2]), "r"(a[3]), "r"(b[0]), "r"(b[1]));
}

// ---------------------------------------------------------------------------
// K0: batch -> domain
// ---------------------------------------------------------------------------
__global__ void dom_kernel(const int* __restrict__ idx) {
    int i = threadIdx.x;
    if (i < BATCH) g_dom[idx[i]] = i >> 3;
}

// ---------------------------------------------------------------------------
// K1: transpose + fp16-round weights: W[g][R][C] (fp32) -> Wt[g][C][R] (fp16)
// ---------------------------------------------------------------------------
__global__ __launch_bounds__(256)
void transpose_kernel(const float* __restrict__ W, __half* __restrict__ Wt,
                      int R, int C) {
    __shared__ float t[32][33];
    const int g  = blockIdx.z;
    const int r0 = blockIdx.y * 32;
    const int c0 = blockIdx.x * 32;
    const float* Wg  = W  + (size_t)g * R * C;
    __half*      Wtg = Wt + (size_t)g * R * C;
    const int tx = threadIdx.x & 31;
    const int ty = threadIdx.x >> 5;
    #pragma unroll
    for (int i = 0; i < 32; i += 8)
        t[ty + i][tx] = Wg[(size_t)(r0 + ty + i) * C + c0 + tx];
    __syncthreads();
    #pragma unroll
    for (int i = 0; i < 32; i += 8)
        Wtg[(size_t)(c0 + ty + i) * R + r0 + tx] = __float2half_rn(t[tx][ty + i]);
}

// ---------------------------------------------------------------------------
// K2: LayerNorm (torch: g*(x-mu)/(std_ddof1+eps)+b), fp16 output
// ---------------------------------------------------------------------------
__global__ __launch_bounds__(256)
void ln_kernel(const float* __restrict__ x,
               const float* __restrict__ G,
               const float* __restrict__ Bn) {
    const int r   = blockIdx.x;
    const int g   = g_dom[r >> 9];
    const int tid = threadIdx.x;

    const float4 v = ((const float4*)(x + (size_t)r * DIM))[tid];
    float s  = v.x + v.y + v.z + v.w;
    float ss = v.x * v.x + v.y * v.y + v.z * v.z + v.w * v.w;

    __shared__ float red_s[8], red_ss[8];
    #pragma unroll
    for (int o = 16; o > 0; o >>= 1) {
        s  += __shfl_down_sync(0xffffffffu, s,  o);
        ss += __shfl_down_sync(0xffffffffu, ss, o);
    }
    if ((tid & 31) == 0) { red_s[tid >> 5] = s; red_ss[tid >> 5] = ss; }
    __syncthreads();
    __shared__ float s_mu, s_inv;
    if (tid == 0) {
        float ts = 0.f, tss = 0.f;
        #pragma unroll
        for (int i = 0; i < 8; i++) { ts += red_s[i]; tss += red_ss[i]; }
        float mu  = ts * (1.0f / DIM);
        float var = (tss - (float)DIM * mu * mu) * (1.0f / (DIM - 1));
        var = fmaxf(var, 0.0f);
        s_mu  = mu;
        s_inv = 1.0f / (sqrtf(var) + LN_EPS);
    }
    __syncthreads();
    const float mu = s_mu, inv = s_inv;
    const float4 gv = ((const float4*)(G  + (size_t)g * DIM))[tid];
    const float4 bv = ((const float4*)(Bn + (size_t)g * DIM))[tid];
    float2 y0, y1;
    y0.x = gv.x * (v.x - mu) * inv + bv.x;
    y0.y = gv.y * (v.y - mu) * inv + bv.y;
    y1.x = gv.z * (v.z - mu) * inv + bv.z;
    y1.y = gv.w * (v.w - mu) * inv + bv.w;
    __half2* dst = (__half2*)(g_ln + (size_t)r * DIM);
    dst[tid * 2 + 0] = __float22half2_rn(y0);
    dst[tid * 2 + 1] = __float22half2_rn(y1);
}

// ---------------------------------------------------------------------------
// K3/K4: fp16 mma.sync grouped GEMM. C[m][n] = epi(sum_k A[m][k]*Bt[g][n][k])
// A, Bt fp16; accum fp32; OUT_HALF selects h (fp16) vs out (fp32+residual).
// ---------------------------------------------------------------------------
template<bool RELU, bool RESID, bool OUT_HALF>
__global__ __launch_bounds__(256, 2)
void mma_gemm(const __half* __restrict__ A, const __half* __restrict__ Bt,
              const float* __restrict__ bias, const float* __restrict__ resid,
              void* __restrict__ Cv, int N, int K) {
    extern __shared__ __half sm[];
    const int tid  = threadIdx.x;
    const int row0 = blockIdx.y * BM;
    const int col0 = blockIdx.x * BN;
    const int g    = g_dom[row0 >> 9];
    const __half* Bg = Bt + (size_t)g * N * K;

    const int lane  = tid & 31;
    const int wid   = tid >> 5;
    const int gid   = lane >> 2;      // 0..7
    const int tg    = lane & 3;       // 0..3
    const int warpm = wid & 1;        // m offset *64
    const int warpn = wid >> 1;       // n offset *32

    // stage loader: per operand 512 16B-chunks (8 halves each), 2 per thread
    auto load_stage = [&](int kt, int s) {
        const int k0 = kt * BKK;
        __half* As = sm + s * 2 * STAGE_HALVES;
        __half* Bs = As + STAGE_HALVES;
        #pragma unroll
        for (int j = 0; j < 2; j++) {
            int c = tid + j * 256;
            int m = c >> 2, kc = (c & 3) << 3;
            cp_async16(&As[m * PADH + kc],
                       A + (size_t)(row0 + m) * K + k0 + kc);
        }
        #pragma unroll
        for (int j = 0; j < 2; j++) {
            int c = tid + j * 256;
            int n = c >> 2, kc = (c & 3) << 3;
            cp_async16(&Bs[n * PADH + kc],
                       Bg + (size_t)(col0 + n) * K + k0 + kc);
        }
        CP_COMMIT();
    };

    float acc[4][4][4];
    #pragma unroll
    for (int i = 0; i < 4; i++)
        #pragma unroll
        for (int j = 0; j < 4; j++)
            #pragma unroll
            for (int q = 0; q < 4; q++) acc[i][j][q] = 0.f;

    const int KT = K / BKK;
    #pragma unroll
    for (int s = 0; s < NSTG - 1; s++) load_stage(s, s);

    for (int kt = 0; kt < KT; kt++) {
        CP_WAIT(NSTG - 2);
        __syncthreads();
        {
            int nx = kt + NSTG - 1;
            if (nx < KT) load_stage(nx, nx & (NSTG - 1));
            else CP_COMMIT();
        }
        const __half* As = sm + (kt & (NSTG - 1)) * 2 * STAGE_HALVES;
        const __half* Bs = As + STAGE_HALVES;
        const __half* Abase = As + (warpm * 64 + gid) * PADH + 2 * tg;
        const __half* Bbase = Bs + (warpn * 32 + gid) * PADH + 2 * tg;
        #pragma unroll
        for (int ks = 0; ks < 2; ks++) {        // two k16 slices per BK=32
            uint32_t a[4][4], b[4][2];
            #pragma unroll
            for (int mf = 0; mf < 4; mf++) {
                const __half* p = Abase + mf * 16 * PADH + ks * 16;
                a[mf][0] = *(const uint32_t*)(p);
                a[mf][1] = *(const uint32_t*)(p + 8 * PADH);
                a[mf][2] = *(const uint32_t*)(p + 8);
                a[mf][3] = *(const uint32_t*)(p + 8 * PADH + 8);
            }
            #pragma unroll
            for (int nf = 0; nf < 4; nf++) {
                const __half* p = Bbase + nf * 8 * PADH + ks * 16;
                b[nf][0] = *(const uint32_t*)(p);
                b[nf][1] = *(const uint32_t*)(p + 8);
            }
            #pragma unroll
            for (int mf = 0; mf < 4; mf++)
                #pragma unroll
                for (int nf = 0; nf < 4; nf++)
                    mma_f16(acc[mf][nf], a[mf], b[nf]);
        }
    }

    // epilogue
    const float* biasg = bias + (size_t)g * N;
    #pragma unroll
    for (int mf = 0; mf < 4; mf++) {
        #pragma unroll
        for (int h = 0; h < 2; h++) {
            const int r = row0 + warpm * 64 + mf * 16 + gid + h * 8;
            const float* rrow = RESID ? (resid + (size_t)r * N) : nullptr;
            #pragma unroll
            for (int nf = 0; nf < 4; nf++) {
                const int cidx = col0 + warpn * 32 + nf * 8 + tg * 2;
                float2 v;
                v.x = acc[mf][nf][h * 2 + 0] + biasg[cidx];
                v.y = acc[mf][nf][h * 2 + 1] + biasg[cidx + 1];
                if (RELU) { v.x = fmaxf(v.x, 0.f); v.y = fmaxf(v.y, 0.f); }
                if (RESID) { v.x += rrow[cidx]; v.y += rrow[cidx + 1]; }
                if (OUT_HALF) {
                    __half2* crow = (__half2*)((__half*)Cv + (size_t)r * N + cidx);
                    *crow = __float22half2_rn(v);
                } else {
                    *(float2*)((float*)Cv + (size_t)r * N + cidx) = v;
                }
            }
        }
    }
}

// ---------------------------------------------------------------------------
extern "C" void kernel_launch(void* const* d_in, const int* in_sizes, int n_in,
                              void* d_out, int out_size) {
    const float* x   = (const float*)d_in[0];
    const int*   idx = (const int*)  d_in[1];
    const float* W1  = (const float*)d_in[2];
    const float* B1  = (const float*)d_in[3];
    const float* W2  = (const float*)d_in[4];
    const float* B2  = (const float*)d_in[5];
    const float* G   = (const float*)d_in[6];
    const float* Bn  = (const float*)d_in[7];
    float*       out = (float*)d_out;

    __half *ln_ptr, *h_ptr, *w1t_ptr, *w2t_ptr;
    cudaGetSymbolAddress((void**)&ln_ptr,  g_ln);
    cudaGetSymbolAddress((void**)&h_ptr,   g_h);
    cudaGetSymbolAddress((void**)&w1t_ptr, g_w1t);
    cudaGetSymbolAddress((void**)&w2t_ptr, g_w2t);

    static bool attr_done = false;
    if (!attr_done) {
        cudaFuncSetAttribute(mma_gemm<true, false, true>,
                             cudaFuncAttributeMaxDynamicSharedMemorySize, SMEM_BYTES);
        cudaFuncSetAttribute(mma_gemm<false, true, false>,
                             cudaFuncAttributeMaxDynamicSharedMemorySize, SMEM_BYTES);
        attr_done = true;
    }

    dom_kernel<<<1, 32>>>(idx);

    // W1[g][D][F] -> g_w1t[g][F][D];  W2[g][F][D] -> g_w2t[g][D][F]
    transpose_kernel<<<dim3(FFN / 32, DIM / 32, GDOM), 256>>>(W1, w1t_ptr, DIM, FFN);
    transpose_kernel<<<dim3(DIM / 32, FFN / 32, GDOM), 256>>>(W2, w2t_ptr, FFN, DIM);

    ln_kernel<<<NTOK, 256>>>(x, G, Bn);

    // gemm1: h = relu(ln @ W1[g] + B1[g]) -> fp16
    mma_gemm<true, false, true><<<dim3(FFN / BN, NTOK / BM), 256, SMEM_BYTES>>>(
        ln_ptr, w1t_ptr, B1, nullptr, h_ptr, FFN, DIM);

    // gemm2: out = x + h @ W2[g] + B2[g] -> fp32
    mma_gemm<false, true, false><<<dim3(DIM / BN, NTOK / BM), 256, SMEM_BYTES>>>(
        h_ptr, w2t_ptr, B2, x, out, DIM, FFN);
}

// round 6
// speedup vs baseline: 6.6714x; 1.0990x over previous
#include <cuda_runtime.h>
#include <cuda_fp16.h>
#include <math.h>
#include <stdint.h>

// Problem constants
#define BATCH   32
#define SEQ     512
#define DIM     1024
#define FFN     2048
#define GDOM    4
#define NTOK    (BATCH * SEQ)
#define LN_EPS  1e-6f

// GEMM tiling: 128x128 CTA, BK=32 (halves), 8 warps (2m x 4n), warp 64x32
#define BM 128
#define BN 128
#define BKK 32
#define NSTG 4
#define PADH 40                              // halves per k-row (32 data + 8 pad)
#define STAGE_HALVES (128 * PADH)            // 5120 halves per operand stage
#define SMEM_BYTES (NSTG * 2 * STAGE_HALVES * 2)   // 81920

// ---------------------------------------------------------------------------
// Scratch (device globals; allocation-free per harness rules)
// ---------------------------------------------------------------------------
__device__ __half g_ln [(size_t)NTOK * DIM];        // 32 MB LN output (fp16)
__device__ __half g_h  [(size_t)NTOK * FFN];        // 64 MB hidden (fp16)
__device__ __half g_w1t[(size_t)GDOM * FFN * DIM];  // 16 MB W1^T [g][F][D]
__device__ __half g_w2t[(size_t)GDOM * DIM * FFN];  // 16 MB W2^T [g][D][F]
__device__ int    g_dom[BATCH];

// ---------------------------------------------------------------------------
// PTX helpers
// ---------------------------------------------------------------------------
__device__ __forceinline__ uint32_t smem_u32(const void* p) {
    uint32_t a;
    asm("{ .reg .u64 t; cvta.to.shared.u64 t, %1; cvt.u32.u64 %0, t; }"
        : "=r"(a) : "l"(p));
    return a;
}
__device__ __forceinline__ void cp_async16(void* s, const void* g) {
    uint32_t sa = smem_u32(s);
    asm volatile("cp.async.cg.shared.global [%0], [%1], 16;" :: "r"(sa), "l"(g));
}
#define CP_COMMIT() asm volatile("cp.async.commit_group;" ::: "memory")
#define CP_WAIT(n)  asm volatile("cp.async.wait_group %0;" :: "n"(n) : "memory")

// ldmatrix x4: four 8x8 b16 matrices, one per output register
__device__ __forceinline__ void ldsm_x4(uint32_t& r0, uint32_t& r1,
                                        uint32_t& r2, uint32_t& r3,
                                        uint32_t addr) {
    asm volatile("ldmatrix.sync.aligned.m8n8.x4.shared.b16 {%0,%1,%2,%3}, [%4];"
                 : "=r"(r0), "=r"(r1), "=r"(r2), "=r"(r3) : "r"(addr));
}

// D += A*B, m16n8k16 row.col f16 inputs, f32 accum
__device__ __forceinline__ void mma_f16(float* c, const uint32_t* a,
                                        const uint32_t* b) {
    asm volatile(
        "mma.sync.aligned.m16n8k16.row.col.f32.f16.f16.f32 "
        "{%0,%1,%2,%3}, {%4,%5,%6,%7}, {%8,%9}, {%0,%1,%2,%3};"
        : "+f"(c[0]), "+f"(c[1]), "+f"(c[2]), "+f"(c[3])
        : "r"(a[0]), "r"(a[1]), "r"(a[2]), "r"(a[3]), "r"(b[0]), "r"(b[1]));
}

// ---------------------------------------------------------------------------
// K0: batch -> domain
// ---------------------------------------------------------------------------
__global__ void dom_kernel(const int* __restrict__ idx) {
    int i = threadIdx.x;
    if (i < BATCH) g_dom[idx[i]] = i >> 3;
}

// ---------------------------------------------------------------------------
// K1: transpose + fp16-round weights: W[g][R][C] (fp32) -> Wt[g][C][R] (fp16)
// ---------------------------------------------------------------------------
__global__ __launch_bounds__(256)
void transpose_kernel(const float* __restrict__ W, __half* __restrict__ Wt,
                      int R, int C) {
    __shared__ float t[32][33];
    const int g  = blockIdx.z;
    const int r0 = blockIdx.y * 32;
    const int c0 = blockIdx.x * 32;
    const float* Wg  = W  + (size_t)g * R * C;
    __half*      Wtg = Wt + (size_t)g * R * C;
    const int tx = threadIdx.x & 31;
    const int ty = threadIdx.x >> 5;
    #pragma unroll
    for (int i = 0; i < 32; i += 8)
        t[ty + i][tx] = Wg[(size_t)(r0 + ty + i) * C + c0 + tx];
    __syncthreads();
    #pragma unroll
    for (int i = 0; i < 32; i += 8)
        Wtg[(size_t)(c0 + ty + i) * R + r0 + tx] = __float2half_rn(t[tx][ty + i]);
}

// ---------------------------------------------------------------------------
// K2: LayerNorm (torch: g*(x-mu)/(std_ddof1+eps)+b), fp16 output
// ---------------------------------------------------------------------------
__global__ __launch_bounds__(256)
void ln_kernel(const float* __restrict__ x,
               const float* __restrict__ G,
               const float* __restrict__ Bn) {
    const int r   = blockIdx.x;
    const int g   = g_dom[r >> 9];
    const int tid = threadIdx.x;

    const float4 v = ((const float4*)(x + (size_t)r * DIM))[tid];
    float s  = v.x + v.y + v.z + v.w;
    float ss = v.x * v.x + v.y * v.y + v.z * v.z + v.w * v.w;

    __shared__ float red_s[8], red_ss[8];
    #pragma unroll
    for (int o = 16; o > 0; o >>= 1) {
        s  += __shfl_down_sync(0xffffffffu, s,  o);
        ss += __shfl_down_sync(0xffffffffu, ss, o);
    }
    if ((tid & 31) == 0) { red_s[tid >> 5] = s; red_ss[tid >> 5] = ss; }
    __syncthreads();
    __shared__ float s_mu, s_inv;
    if (tid == 0) {
        float ts = 0.f, tss = 0.f;
        #pragma unroll
        for (int i = 0; i < 8; i++) { ts += red_s[i]; tss += red_ss[i]; }
        float mu  = ts * (1.0f / DIM);
        float var = (tss - (float)DIM * mu * mu) * (1.0f / (DIM - 1));
        var = fmaxf(var, 0.0f);
        s_mu  = mu;
        s_inv = 1.0f / (sqrtf(var) + LN_EPS);
    }
    __syncthreads();
    const float mu = s_mu, inv = s_inv;
    const float4 gv = ((const float4*)(G  + (size_t)g * DIM))[tid];
    const float4 bv = ((const float4*)(Bn + (size_t)g * DIM))[tid];
    float2 y0, y1;
    y0.x = gv.x * (v.x - mu) * inv + bv.x;
    y0.y = gv.y * (v.y - mu) * inv + bv.y;
    y1.x = gv.z * (v.z - mu) * inv + bv.z;
    y1.y = gv.w * (v.w - mu) * inv + bv.w;
    __half2* dst = (__half2*)(g_ln + (size_t)r * DIM);
    dst[tid * 2 + 0] = __float22half2_rn(y0);
    dst[tid * 2 + 1] = __float22half2_rn(y1);
}

// ---------------------------------------------------------------------------
// K3/K4: fp16 mma.sync grouped GEMM with ldmatrix fragment loads.
// C[m][n] = epi(sum_k A[m][k]*Bt[g][n][k])
// ---------------------------------------------------------------------------
template<bool RELU, bool RESID, bool OUT_HALF>
__global__ __launch_bounds__(256, 2)
void mma_gemm(const __half* __restrict__ A, const __half* __restrict__ Bt,
              const float* __restrict__ bias, const float* __restrict__ resid,
              void* __restrict__ Cv, int N, int K) {
    extern __shared__ __half sm[];
    const int tid  = threadIdx.x;
    const int row0 = blockIdx.y * BM;
    const int col0 = blockIdx.x * BN;
    const int g    = g_dom[row0 >> 9];
    const __half* Bg = Bt + (size_t)g * N * K;

    const int lane  = tid & 31;
    const int wid   = tid >> 5;
    const int gid   = lane >> 2;      // 0..7
    const int tg    = lane & 3;       // 0..3
    const int warpm = wid & 1;        // m offset *64
    const int warpn = wid >> 1;       // n offset *32

    const uint32_t sm_base = smem_u32(sm);

    // ldmatrix per-lane address offsets (in halves, relative to operand base)
    // A x4 matrices: (m0-7,k0),(m8-15,k0),(m0-7,k8),(m8-15,k8)
    const uint32_t aoff_h =
        (uint32_t)((warpm * 64 + (lane & 7) + ((lane >> 3) & 1) * 8) * PADH
                   + (lane >> 4) * 8);
    // B x4 matrices: (n0-7,k0),(n0-7,k8),(n8-15,k0),(n8-15,k8)
    const uint32_t boff_h =
        (uint32_t)((warpn * 32 + (lane & 7) + (lane >> 4) * 8) * PADH
                   + ((lane >> 3) & 1) * 8);

    // stage loader: per operand 512 16B-chunks (8 halves each), 2 per thread
    auto load_stage = [&](int kt, int s) {
        const int k0 = kt * BKK;
        __half* As = sm + s * 2 * STAGE_HALVES;
        __half* Bs = As + STAGE_HALVES;
        #pragma unroll
        for (int j = 0; j < 2; j++) {
            int c = tid + j * 256;
            int m = c >> 2, kc = (c & 3) << 3;
            cp_async16(&As[m * PADH + kc],
                       A + (size_t)(row0 + m) * K + k0 + kc);
        }
        #pragma unroll
        for (int j = 0; j < 2; j++) {
            int c = tid + j * 256;
            int n = c >> 2, kc = (c & 3) << 3;
            cp_async16(&Bs[n * PADH + kc],
                       Bg + (size_t)(col0 + n) * K + k0 + kc);
        }
        CP_COMMIT();
    };

    float acc[4][4][4];
    #pragma unroll
    for (int i = 0; i < 4; i++)
        #pragma unroll
        for (int j = 0; j < 4; j++)
            #pragma unroll
            for (int q = 0; q < 4; q++) acc[i][j][q] = 0.f;

    const int KT = K / BKK;
    #pragma unroll
    for (int s = 0; s < NSTG - 1; s++) load_stage(s, s);

    for (int kt = 0; kt < KT; kt++) {
        CP_WAIT(NSTG - 2);
        __syncthreads();
        {
            int nx = kt + NSTG - 1;
            if (nx < KT) load_stage(nx, nx & (NSTG - 1));
            else CP_COMMIT();
        }
        const uint32_t Abase = sm_base
            + (uint32_t)((kt & (NSTG - 1)) * 2 * STAGE_HALVES) * 2u;
        const uint32_t Bbase = Abase + STAGE_HALVES * 2u;
        const uint32_t Aaddr = Abase + aoff_h * 2u;
        const uint32_t Baddr = Bbase + boff_h * 2u;
        #pragma unroll
        for (int ks = 0; ks < 2; ks++) {        // two k16 slices per BK=32
            uint32_t a[4][4], b[4][2];
            #pragma unroll
            for (int mf = 0; mf < 4; mf++)
                ldsm_x4(a[mf][0], a[mf][1], a[mf][2], a[mf][3],
                        Aaddr + (uint32_t)(mf * 16 * PADH + ks * 16) * 2u);
            ldsm_x4(b[0][0], b[0][1], b[1][0], b[1][1],
                    Baddr + (uint32_t)(ks * 16) * 2u);
            ldsm_x4(b[2][0], b[2][1], b[3][0], b[3][1],
                    Baddr + (uint32_t)(16 * PADH + ks * 16) * 2u);
            #pragma unroll
            for (int mf = 0; mf < 4; mf++)
                #pragma unroll
                for (int nf = 0; nf < 4; nf++)
                    mma_f16(acc[mf][nf], a[mf], b[nf]);
        }
    }

    // epilogue
    const float* biasg = bias + (size_t)g * N;
    #pragma unroll
    for (int mf = 0; mf < 4; mf++) {
        #pragma unroll
        for (int h = 0; h < 2; h++) {
            const int r = row0 + warpm * 64 + mf * 16 + gid + h * 8;
            const float* rrow = RESID ? (resid + (size_t)r * N) : nullptr;
            #pragma unroll
            for (int nf = 0; nf < 4; nf++) {
                const int cidx = col0 + warpn * 32 + nf * 8 + tg * 2;
                float2 v;
                v.x = acc[mf][nf][h * 2 + 0] + biasg[cidx];
                v.y = acc[mf][nf][h * 2 + 1] + biasg[cidx + 1];
                if (RELU) { v.x = fmaxf(v.x, 0.f); v.y = fmaxf(v.y, 0.f); }
                if (RESID) { v.x += rrow[cidx]; v.y += rrow[cidx + 1]; }
                if (OUT_HALF) {
                    __half2* crow = (__half2*)((__half*)Cv + (size_t)r * N + cidx);
                    *crow = __float22half2_rn(v);
                } else {
                    *(float2*)((float*)Cv + (size_t)r * N + cidx) = v;
                }
            }
        }
    }
}

// ---------------------------------------------------------------------------
extern "C" void kernel_launch(void* const* d_in, const int* in_sizes, int n_in,
                              void* d_out, int out_size) {
    const float* x   = (const float*)d_in[0];
    const int*   idx = (const int*)  d_in[1];
    const float* W1  = (const float*)d_in[2];
    const float* B1  = (const float*)d_in[3];
    const float* W2  = (const float*)d_in[4];
    const float* B2  = (const float*)d_in[5];
    const float* G   = (const float*)d_in[6];
    const float* Bn  = (const float*)d_in[7];
    float*       out = (float*)d_out;

    __half *ln_ptr, *h_ptr, *w1t_ptr, *w2t_ptr;
    cudaGetSymbolAddress((void**)&ln_ptr,  g_ln);
    cudaGetSymbolAddress((void**)&h_ptr,   g_h);
    cudaGetSymbolAddress((void**)&w1t_ptr, g_w1t);
    cudaGetSymbolAddress((void**)&w2t_ptr, g_w2t);

    static bool attr_done = false;
    if (!attr_done) {
        cudaFuncSetAttribute(mma_gemm<true, false, true>,
                             cudaFuncAttributeMaxDynamicSharedMemorySize, SMEM_BYTES);
        cudaFuncSetAttribute(mma_gemm<false, true, false>,
                             cudaFuncAttributeMaxDynamicSharedMemorySize, SMEM_BYTES);
        attr_done = true;
    }

    dom_kernel<<<1, 32>>>(idx);

    // W1[g][D][F] -> g_w1t[g][F][D];  W2[g][F][D] -> g_w2t[g][D][F]
    transpose_kernel<<<dim3(FFN / 32, DIM / 32, GDOM), 256>>>(W1, w1t_ptr, DIM, FFN);
    transpose_kernel<<<dim3(DIM / 32, FFN / 32, GDOM), 256>>>(W2, w2t_ptr, FFN, DIM);

    ln_kernel<<<NTOK, 256>>>(x, G, Bn);

    // gemm1: h = relu(ln @ W1[g] + B1[g]) -> fp16
    mma_gemm<true, false, true><<<dim3(FFN / BN, NTOK / BM), 256, SMEM_BYTES>>>(
        ln_ptr, w1t_ptr, B1, nullptr, h_ptr, FFN, DIM);

    // gemm2: out = x + h @ W2[g] + B2[g] -> fp32
    mma_gemm<false, true, false><<<dim3(DIM / BN, NTOK / BM), 256, SMEM_BYTES>>>(
        h_ptr, w2t_ptr, B2, x, out, DIM, FFN);
}